// round 11
// baseline (speedup 1.0000x reference)
#include <cuda_runtime.h>
#include <cstdint>

// ---------------------------------------------------------------------------
// minLSTM cell, fused: grouped linears + gate math + parallel scan via
// decoupled lookback (single data pass, full-chip grid).
//
// Shapes: x (B=4, S=8192, D=1024), W* (128 groups, 8, 8), out (4, 8192, 1024).
//
// Exact algebraic rewrite of the reference:
//   F,I,G = grouped 8x8 linears
//   eF=exp(-F), eI=exp(-I), s = 2+eF+eI
//   f = (1+eI)/s      (exp(EPS) cumsum factor dropped: bias <= 8.2e-5)
//   i = (1+eF)/s
//   g = G>=0 ? G+0.5+1e-8 : sigmoid(G)
//   h_t = f_t * h_{t-1} + i_t * g_t,  h_{-1} = 0
//
// Tile = (chain of 32 channels) x (chunk of 128 timesteps); 8192 blocks of
// 256 threads (8 warps x 16 t). Chunk-major block order => predecessor tiles
// have lower blockIdx (forward progress). Lookback spin is nanosleep-backed
// and bounded, so a protocol bug degrades to a wrong answer, never a hang.
// ---------------------------------------------------------------------------

namespace {
constexpr int kS       = 8192;
constexpr int kD       = 1024;
constexpr int kWarps   = 8;
constexpr int kThreads = kWarps * 32;            // 256
constexpr int kTper    = 16;                     // timesteps per thread
constexpr int kChunkT  = kWarps * kTper;         // 128 timesteps per chunk
constexpr int kNChunk  = kS / kChunkT;           // 64
constexpr int kNChain  = 128;                    // 4 batches * 32 group-quads
constexpr int kNState  = kNChain * kNChunk;      // 8192
constexpr float kNegLog2e = -1.4426950408889634f;
}  // namespace

__device__ float g_wf2[128 * 64];                // Wf * -log2(e)
__device__ float g_wi2[128 * 64];                // Wi * -log2(e)

// Decoupled-lookback state (flag: 0 = none, 1 = aggregate, 2 = prefix).
__device__ int    g_flag[kNState];
__device__ float2 g_agg [kNState][32];
__device__ float  g_pref[kNState][32];

__global__ void prep_kernel(const float* __restrict__ Wf,
                            const float* __restrict__ Wi) {
  int i = blockIdx.x * blockDim.x + threadIdx.x;
  if (i < 128 * 64) {
    g_wf2[i] = Wf[i] * kNegLog2e;
    g_wi2[i] = Wi[i] * kNegLog2e;
  }
  if (i < kNState) g_flag[i] = 0;
}

__device__ __forceinline__ float ex2f(float x) {
  float r;
  asm("ex2.approx.f32 %0, %1;" : "=f"(r) : "f"(x));
  return r;
}
__device__ __forceinline__ float frcp(float x) {
  float r;
  asm("rcp.approx.f32 %0, %1;" : "=f"(r) : "f"(x));
  return r;
}

__global__ __launch_bounds__(kThreads, 2) void minlstm_kernel(
    const float* __restrict__ x, const float* __restrict__ Wh,
    float* __restrict__ out) {
  const int chunk   = blockIdx.x >> 7;           // chunk-major: progress order
  const int chain   = blockIdx.x & 127;
  const int b       = chain >> 5;
  const int gq      = chain & 31;                // group-quad (4 groups, 32 ch)
  const int w       = threadIdx.x >> 5;          // warp = time slab
  const int c       = threadIdx.x & 31;          // lane = channel
  const int stateid = chain * kNChunk + chunk;

  // Per-channel weight rows; 8 lanes of a group share x inputs.
  const int row = gq * 32 + c;
  const float4 wf0 = *reinterpret_cast<const float4*>(g_wf2 + row * 8);
  const float4 wf1 = *reinterpret_cast<const float4*>(g_wf2 + row * 8 + 4);
  const float4 wi0 = *reinterpret_cast<const float4*>(g_wi2 + row * 8);
  const float4 wi1 = *reinterpret_cast<const float4*>(g_wi2 + row * 8 + 4);
  const float4 wh0 = *reinterpret_cast<const float4*>(Wh + row * 8);
  const float4 wh1 = *reinterpret_cast<const float4*>(Wh + row * 8 + 4);

  const int t0 = chunk * kChunkT + w * kTper;
  const float* xp = x + ((size_t)b * kS + t0) * kD + gq * 32 + (c & 24);

  float aj[kTper], bj[kTper];
  float A = 1.f, Bv = 0.f;                       // running affine for this slab
#pragma unroll
  for (int j = 0; j < kTper; j++) {
    const float4 xa = *reinterpret_cast<const float4*>(xp + (size_t)j * kD);
    const float4 xb = *reinterpret_cast<const float4*>(xp + (size_t)j * kD + 4);

    float Fd = xa.x * wf0.x;                     // pre-scaled by -log2e
    Fd = fmaf(xa.y, wf0.y, Fd); Fd = fmaf(xa.z, wf0.z, Fd); Fd = fmaf(xa.w, wf0.w, Fd);
    Fd = fmaf(xb.x, wf1.x, Fd); Fd = fmaf(xb.y, wf1.y, Fd);
    Fd = fmaf(xb.z, wf1.z, Fd); Fd = fmaf(xb.w, wf1.w, Fd);

    float Id = xa.x * wi0.x;
    Id = fmaf(xa.y, wi0.y, Id); Id = fmaf(xa.z, wi0.z, Id); Id = fmaf(xa.w, wi0.w, Id);
    Id = fmaf(xb.x, wi1.x, Id); Id = fmaf(xb.y, wi1.y, Id);
    Id = fmaf(xb.z, wi1.z, Id); Id = fmaf(xb.w, wi1.w, Id);

    float G = xa.x * wh0.x;
    G = fmaf(xa.y, wh0.y, G); G = fmaf(xa.z, wh0.z, G); G = fmaf(xa.w, wh0.w, G);
    G = fmaf(xb.x, wh1.x, G); G = fmaf(xb.y, wh1.y, G);
    G = fmaf(xb.z, wh1.z, G); G = fmaf(xb.w, wh1.w, G);

    const float eF = ex2f(Fd);                   // e^{-F}
    const float eI = ex2f(Id);                   // e^{-I}
    const float s  = 2.f + eF + eI;
    const float rd = frcp(s);
    const float f  = fmaf(eI, rd, rd);           // (1+eI)/s
    const float ic = fmaf(eF, rd, rd);           // (1+eF)/s
    const float g  = (G >= 0.f) ? (G + 0.5f + 1e-8f)
                                : frcp(1.f + ex2f(G * kNegLog2e));
    const float v  = ic * g;

    aj[j] = f;
    bj[j] = v;
    A *= f;
    Bv = fmaf(f, Bv, v);
  }

  __shared__ float2 sc[kWarps][32];
  __shared__ float  Hs[32];
  sc[w][c] = make_float2(A, Bv);
  __syncthreads();

  // Exclusive prefix over earlier slabs for this channel.
  float Ae = 1.f, Be = 0.f;
  for (int k = 0; k < w; k++) {
    const float2 p = sc[k][c];
    Be = fmaf(p.x, Be, p.y);
    Ae *= p.x;
  }

  // Last slab publishes block aggregate (or, for chunk 0, the final prefix).
  float Ablk = 0.f, Bblk = 0.f;
  if (w == kWarps - 1) {
    Ablk = A * Ae;
    Bblk = fmaf(A, Be, Bv);
    if (chunk == 0) {
      g_pref[stateid][c] = Bblk;                 // H_prev = 0
      __threadfence();
      __syncwarp();
      if (c == 0) *(volatile int*)&g_flag[stateid] = 2;
    } else if (chunk < kNChunk - 1) {
      g_agg[stateid][c] = make_float2(Ablk, Bblk);
      __threadfence();
      __syncwarp();
      if (c == 0) *(volatile int*)&g_flag[stateid] = 1;
    }
  }

  // Lookback (warp 0, lane = channel): h at the end of chunk-1.
  if (w == 0) {
    float Hp = 0.f;
    if (chunk > 0) {
      float Aa = 1.f, Ba = 0.f;
      int k = stateid - 1;
      int guard = 0;
      for (;;) {
        int fl = *(volatile int*)&g_flag[k];
        if (fl == 0) {
          if (++guard > (1 << 22)) break;        // safety valve: never hang
          __nanosleep(32);
          continue;
        }
        __threadfence();                         // acquire
        if (fl == 2) {
          Hp = fmaf(Aa, g_pref[k][c], Ba);
          break;
        }
        const float2 ag = g_agg[k][c];
        Ba = fmaf(Aa, ag.y, Ba);
        Aa *= ag.x;
        --k;                                     // chunk 0 always reaches 2
      }
    }
    Hs[c] = Hp;
  }
  __syncthreads();

  const float Hp = Hs[c];

  // Upgrade own state to inclusive prefix to cap successors' lookback depth.
  if (w == kWarps - 1 && chunk > 0 && chunk < kNChunk - 1) {
    g_pref[stateid][c] = fmaf(Ablk, Hp, Bblk);
    __threadfence();
    __syncwarp();
    if (c == 0) *(volatile int*)&g_flag[stateid] = 2;
  }

  // Apply carry and emit; lanes are 32 contiguous floats -> coalesced 128B.
  float h = fmaf(Ae, Hp, Be);
  float* op = out + ((size_t)b * kS + t0) * kD + gq * 32 + c;
#pragma unroll
  for (int j = 0; j < kTper; j++) {
    h = fmaf(aj[j], h, bj[j]);
    op[(size_t)j * kD] = h;
  }
}

extern "C" void kernel_launch(void* const* d_in, const int* in_sizes, int n_in,
                              void* d_out, int out_size) {
  (void)in_sizes; (void)n_in; (void)out_size;
  const float* x  = (const float*)d_in[0];
  const float* Wf = (const float*)d_in[1];
  const float* Wi = (const float*)d_in[2];
  const float* Wh = (const float*)d_in[3];
  float* out = (float*)d_out;

  prep_kernel<<<32, 256>>>(Wf, Wi);              // also zeroes lookback flags
  minlstm_kernel<<<kNState, kThreads>>>(x, Wh, out);
}

// round 12
// speedup vs baseline: 1.2903x; 1.2903x over previous
#include <cuda_runtime.h>
#include <cstdint>

// ---------------------------------------------------------------------------
// minLSTM cell, fused: grouped linears + gate math + scan.
// R12: chain-resident CTAs split by group-PAIR (16 channels) so each SM hosts
// two independent CTAs (barrier/scan stalls of one hidden by the other).
// Scalar FFMA dots; Wf/Wi pre-scaled by -log2(e); EPS cumsum factor dropped.
//
// Shapes: x (B=4, S=8192, D=1024), W* (128 groups, 8, 8), out (4, 8192, 1024).
//
// Exact algebraic rewrite of the reference:
//   F,I,G = grouped 8x8 linears
//   eF=exp(-F), eI=exp(-I), s = 2+eF+eI
//   f = (1+eI)/s      (exp(EPS) factor dropped: bias <= 8.2e-5 << 1e-3)
//   i = (1+eF)/s
//   g = G>=0 ? G+0.5+1e-8 : sigmoid(G)
//   h_t = f_t * h_{t-1} + i_t * g_t,  h_{-1} = 0
//
// CTA = (batch, group-pair): 256 CTAs x 256 threads. Warp = 2 half-slabs of
// 16 channels; 8 warps x 2 halves x 16 t = 256 timesteps per iteration,
// 32 iterations. Carry via double-buffered smem. No inter-CTA comms.
// ---------------------------------------------------------------------------

namespace {
constexpr int kS       = 8192;
constexpr int kD       = 1024;
constexpr int kWarps   = 8;
constexpr int kThreads = kWarps * 32;            // 256
constexpr int kTper    = 16;                     // timesteps per thread
constexpr int kIterT   = kWarps * 2 * kTper;     // 256 timesteps per iteration
constexpr int kNIter   = kS / kIterT;            // 32
constexpr int kNCta    = 256;                    // 4 batches * 64 group-pairs
constexpr float kNegLog2e = -1.4426950408889634f;
}  // namespace

__device__ float g_wf2[128 * 64];                // Wf * -log2(e)
__device__ float g_wi2[128 * 64];                // Wi * -log2(e)

__global__ void prep_kernel(const float* __restrict__ Wf,
                            const float* __restrict__ Wi) {
  int i = blockIdx.x * blockDim.x + threadIdx.x;
  if (i < 128 * 64) {
    g_wf2[i] = Wf[i] * kNegLog2e;
    g_wi2[i] = Wi[i] * kNegLog2e;
  }
}

__device__ __forceinline__ float ex2f(float x) {
  float r;
  asm("ex2.approx.f32 %0, %1;" : "=f"(r) : "f"(x));
  return r;
}
__device__ __forceinline__ float frcp(float x) {
  float r;
  asm("rcp.approx.f32 %0, %1;" : "=f"(r) : "f"(x));
  return r;
}

__global__ __launch_bounds__(kThreads, 2) void minlstm_kernel(
    const float* __restrict__ x, const float* __restrict__ Wh,
    float* __restrict__ out) {
  const int b    = blockIdx.x >> 6;              // batch
  const int gp   = blockIdx.x & 63;              // group-pair (2 groups, 16 ch)
  const int w    = threadIdx.x >> 5;             // warp = 32-t slab
  const int c    = threadIdx.x & 31;
  const int ch   = c & 15;                       // channel within pair
  const int half = c >> 4;                       // half-slab (16 t each)

  // Per-channel weight rows; 8 lanes of a group share x inputs.
  const int row = gp * 16 + ch;
  const float4 wf0 = *reinterpret_cast<const float4*>(g_wf2 + row * 8);
  const float4 wf1 = *reinterpret_cast<const float4*>(g_wf2 + row * 8 + 4);
  const float4 wi0 = *reinterpret_cast<const float4*>(g_wi2 + row * 8);
  const float4 wi1 = *reinterpret_cast<const float4*>(g_wi2 + row * 8 + 4);
  const float4 wh0 = *reinterpret_cast<const float4*>(Wh + row * 8);
  const float4 wh1 = *reinterpret_cast<const float4*>(Wh + row * 8 + 4);

  __shared__ float2 sc[kWarps][16];              // per-warp inclusive agg
  __shared__ float  Hs[2][16];                   // double-buffered carry
  if (threadIdx.x < 16) { Hs[0][threadIdx.x] = 0.f; Hs[1][threadIdx.x] = 0.f; }

  const float* xg = x + (size_t)b * kS * kD + gp * 16 + (ch & 8);
  float* obase    = out + (size_t)b * kS * kD + gp * 16 + ch;

  for (int iter = 0; iter < kNIter; iter++) {
    const int t0 = iter * kIterT + w * (2 * kTper) + half * kTper;
    const float* xp = xg + (size_t)t0 * kD;

    float aj[kTper], bj[kTper];
    float A = 1.f, Bv = 0.f;                     // running affine, this half
#pragma unroll
    for (int j = 0; j < kTper; j++) {
      const float4 xa = *reinterpret_cast<const float4*>(xp + (size_t)j * kD);
      const float4 xb = *reinterpret_cast<const float4*>(xp + (size_t)j * kD + 4);

      float Fd = xa.x * wf0.x;                   // pre-scaled by -log2e
      Fd = fmaf(xa.y, wf0.y, Fd); Fd = fmaf(xa.z, wf0.z, Fd); Fd = fmaf(xa.w, wf0.w, Fd);
      Fd = fmaf(xb.x, wf1.x, Fd); Fd = fmaf(xb.y, wf1.y, Fd);
      Fd = fmaf(xb.z, wf1.z, Fd); Fd = fmaf(xb.w, wf1.w, Fd);

      float Id = xa.x * wi0.x;
      Id = fmaf(xa.y, wi0.y, Id); Id = fmaf(xa.z, wi0.z, Id); Id = fmaf(xa.w, wi0.w, Id);
      Id = fmaf(xb.x, wi1.x, Id); Id = fmaf(xb.y, wi1.y, Id);
      Id = fmaf(xb.z, wi1.z, Id); Id = fmaf(xb.w, wi1.w, Id);

      float G = xa.x * wh0.x;
      G = fmaf(xa.y, wh0.y, G); G = fmaf(xa.z, wh0.z, G); G = fmaf(xa.w, wh0.w, G);
      G = fmaf(xb.x, wh1.x, G); G = fmaf(xb.y, wh1.y, G);
      G = fmaf(xb.z, wh1.z, G); G = fmaf(xb.w, wh1.w, G);

      const float eF = ex2f(Fd);                 // e^{-F}
      const float eI = ex2f(Id);                 // e^{-I}
      const float s  = 2.f + eF + eI;
      const float rd = frcp(s);
      const float f  = fmaf(eI, rd, rd);         // (1+eI)/s
      const float ic = fmaf(eF, rd, rd);         // (1+eF)/s
      const float g  = (G >= 0.f) ? (G + 0.5f + 1e-8f)
                                  : frcp(1.f + ex2f(G * kNegLog2e));
      const float v  = ic * g;

      aj[j] = f;
      bj[j] = v;
      A *= f;
      Bv = fmaf(f, Bv, v);
    }

    // Combine the two half-slabs within the warp (half0 = earlier in time).
    const float A0 = __shfl_sync(0xffffffffu, A, ch);
    const float B0 = __shfl_sync(0xffffffffu, Bv, ch);
    if (half) sc[w][ch] = make_float2(A * A0, fmaf(A, B0, Bv));
    __syncthreads();                             // sc visible; Hs stable

    // Exclusive prefix over earlier warps (32-t slabs), then own half0.
    float Ae = 1.f, Be = 0.f;
    for (int k = 0; k < w; k++) {
      const float2 p = sc[k][ch];
      Be = fmaf(p.x, Be, p.y);
      Ae *= p.x;
    }
    if (half) {
      Be = fmaf(A0, Be, B0);
      Ae *= A0;
    }

    const float Hp = Hs[iter & 1][ch];           // carry entering iteration

    // Last half-slab publishes next carry.
    if (w == kWarps - 1 && half) {
      Hs[(iter + 1) & 1][ch] = fmaf(A * Ae, Hp, fmaf(A, Be, Bv));
    }
    __syncthreads();                             // sc reads done before reuse

    // Apply carry and emit; 16 lanes -> contiguous 64B per timestep.
    float h = fmaf(Ae, Hp, Be);
    float* op = obase + (size_t)t0 * kD;
#pragma unroll
    for (int j = 0; j < kTper; j++) {
      h = fmaf(aj[j], h, bj[j]);
      op[(size_t)j * kD] = h;
    }
  }
}

extern "C" void kernel_launch(void* const* d_in, const int* in_sizes, int n_in,
                              void* d_out, int out_size) {
  (void)in_sizes; (void)n_in; (void)out_size;
  const float* x  = (const float*)d_in[0];
  const float* Wf = (const float*)d_in[1];
  const float* Wi = (const float*)d_in[2];
  const float* Wh = (const float*)d_in[3];
  float* out = (float*)d_out;

  prep_kernel<<<32, 256>>>(Wf, Wi);
  minlstm_kernel<<<kNCta, kThreads>>>(x, Wh, out);
}